// round 6
// baseline (speedup 1.0000x reference)
#include <cuda_runtime.h>
#include <math.h>

// Problem constants (fixed by the reference)
#define NN   10000            // nodes
#define NB   32               // batch
#define DIN  64
#define DOUT 64
#define FF   128              // DIN + DOUT
#define NE   160000           // edges
#define MM   (NN*NB)          // 320000 "rows" (node-major: m = n*32 + b)
#define BFLT (NB*FF)          // 4096 floats per node (full width)
#define V4F  (BFLT/4)         // 1024 float4 per node (full width)
#define V4H  (NB*DOUT/4)      // 512 float4 per node (half width)

typedef unsigned long long u64;

// packed 2xfp32 FMA (Blackwell FFMA2, PTX-only)
#define FMA2(d, a, b) asm("fma.rn.f32x2 %0, %1, %2, %0;" : "+l"(d) : "l"(a), "l"(b))
#define PACK2(d, f)   asm("mov.b64 %0, {%1, %1};" : "=l"(d) : "r"(f))
#define UNPACK2(lo, hi, d) asm("mov.b64 {%0, %1}, %2;" : "=r"(lo), "=r"(hi) : "l"(d))

// ---------------- scratch (device globals; allocation-free) ----------------
__device__ __align__(16) float g_X0[MM*FF];    // concat(inputs, hx), [n][b][f]
__device__ __align__(16) float g_X1[MM*FF];    // A(x0)
__device__ __align__(16) float g_X2[MM*FF];    // 2A(x1) - x0
__device__ __align__(16) float g_RH[MM*DOUT];  // r*hx               [n][b][64]
__device__ __align__(16) float g_D1[MM*DOUT];  // A(r*hx)
__device__ __align__(16) float g_D2[MM*DOUT];  // 2A(D1) - RH
__device__ __align__(16) float g_Z [MM*DOUT];  // update gate z
__device__ int    g_cnt[NN];
__device__ int    g_rs [NN+1];   // CSR row starts (by destination row)
__device__ int    g_cur[NN];
__device__ __align__(8) float2 g_epack[NE];   // {col as int bits, weight}
__device__ int    g_is64;        // edge_index dtype flag

// ---------------- kernel 1: zero counters + dtype detect ----------------
// If data is int64, all values interpreted as int64 lie in [0, NN).
// If data is int32, the int64 view packs two node ids: lo + hi*2^32 >= NN
// unless hi==0 (p=1e-4 per elem; 256 elems -> p_false ~ 0).
__global__ void k_zero_detect(const long long* __restrict__ ei) {
    int i = blockIdx.x*256 + threadIdx.x;
    if (i < NN) g_cnt[i] = 0;
    if (blockIdx.x == 0) {
        __shared__ int bad;
        if (threadIdx.x == 0) bad = 0;
        __syncthreads();
        long long v = ei[threadIdx.x];       // in-bounds either dtype
        if (v < 0 || v >= NN) atomicOr(&bad, 1);
        __syncthreads();
        if (threadIdx.x == 0) g_is64 = bad ? 0 : 1;
    }
}

// ---------------- kernel 2: histogram (blocks 0..624) + build X0 (rest) ----
#define HIST_BLKS (NE/256)     // 625
__global__ void k_histbuild(const void* __restrict__ eiv,
                            const float* __restrict__ in,
                            const float* __restrict__ hx) {
    if (blockIdx.x < HIST_BLKS) {
        int e = blockIdx.x*256 + threadIdx.x;
        int r;
        if (g_is64) r = (int)((const long long*)eiv)[e];
        else        r = ((const int*)eiv)[e];
        atomicAdd(&g_cnt[r], 1);
    } else {
        int n = blockIdx.x - HIST_BLKS;
        for (int i = threadIdx.x; i < NB*DIN; i += 256) {
            int b = i >> 6, f = i & 63;
            g_X0[n*BFLT + b*FF + f]      = in[b*(NN*DIN) + n*DIN + f];
            g_X0[n*BFLT + b*FF + 64 + f] = hx[b*(NN*DOUT) + n*DOUT + f];
        }
    }
}

// ---------------- kernel 3: single-block scan + CSR fill ----------------
__global__ void k_scanfill(const void* __restrict__ eiv,
                           const float* __restrict__ ew) {
    __shared__ int sums[1024];
    int t = threadIdx.x;
    const int CH = 10;                  // 1024*10 >= 10000
    int base = t*CH;
    int loc[CH];
    int s = 0;
    #pragma unroll
    for (int i = 0; i < CH; i++) {
        int idx = base + i;
        int v = (idx < NN) ? g_cnt[idx] : 0;
        loc[i] = s; s += v;
    }
    sums[t] = s;
    __syncthreads();
    for (int off = 1; off < 1024; off <<= 1) {
        int v = (t >= off) ? sums[t-off] : 0;
        __syncthreads();
        sums[t] += v;
        __syncthreads();
    }
    int prev = (t > 0) ? sums[t-1] : 0;
    #pragma unroll
    for (int i = 0; i < CH; i++) {
        int idx = base + i;
        if (idx < NN) {
            int v = prev + loc[i];
            g_rs[idx] = v;
            g_cur[idx] = v;
        }
    }
    if (t == 1023) g_rs[NN] = sums[1023];
    __syncthreads();
    // fill (atomic cursors; 1024 threads sweep all edges)
    int is64 = g_is64;
    for (int e = t; e < NE; e += 1024) {
        int r, c;
        if (is64) {
            r = (int)((const long long*)eiv)[e];
            c = (int)((const long long*)eiv)[NE + e];
        } else {
            r = ((const int*)eiv)[e];
            c = ((const int*)eiv)[NE + e];
        }
        int pos = atomicAdd(&g_cur[r], 1);
        g_epack[pos] = make_float2(__int_as_float(c), ew[e]);
    }
}

// ---------------- graph conv (CSR gather-reduce, feature-sliced) ----------------
// out[n] = scale * sum_{e in row n} w_e * x[col_e]  + (sub ? -base[n] : 0)
// NV4 = float4 elements per node (1024 full-width, 512 half-width)
template<int NV4>
__global__ __launch_bounds__(256) void k_conv(const float4* __restrict__ x,
                       const float4* __restrict__ base,
                       float4* __restrict__ out,
                       float scale, int sub) {
    int n   = blockIdx.x;
    int idx = blockIdx.y*256 + threadIdx.x;     // float4 index within node
    const float4* xb = x + idx;
    float4 acc = make_float4(0.f, 0.f, 0.f, 0.f);
    int e0 = __ldg(&g_rs[n]);
    int e1 = __ldg(&g_rs[n+1]);
    int e = e0;
    for (; e + 2 <= e1; e += 2) {
        float2 p0 = __ldg(&g_epack[e]);
        float2 p1 = __ldg(&g_epack[e+1]);
        float4 v0 = __ldg(xb + __float_as_int(p0.x)*NV4);
        float4 v1 = __ldg(xb + __float_as_int(p1.x)*NV4);
        acc.x = fmaf(p0.y, v0.x, acc.x);
        acc.y = fmaf(p0.y, v0.y, acc.y);
        acc.z = fmaf(p0.y, v0.z, acc.z);
        acc.w = fmaf(p0.y, v0.w, acc.w);
        acc.x = fmaf(p1.y, v1.x, acc.x);
        acc.y = fmaf(p1.y, v1.y, acc.y);
        acc.z = fmaf(p1.y, v1.z, acc.z);
        acc.w = fmaf(p1.y, v1.w, acc.w);
    }
    if (e < e1) {
        float2 p0 = __ldg(&g_epack[e]);
        float4 v0 = __ldg(xb + __float_as_int(p0.x)*NV4);
        acc.x = fmaf(p0.y, v0.x, acc.x);
        acc.y = fmaf(p0.y, v0.y, acc.y);
        acc.z = fmaf(p0.y, v0.z, acc.z);
        acc.w = fmaf(p0.y, v0.w, acc.w);
    }
    float4 r;
    if (sub) {
        float4 b = __ldg(&base[n*NV4 + idx]);
        r = make_float4(fmaf(scale, acc.x, -b.x), fmaf(scale, acc.y, -b.y),
                        fmaf(scale, acc.z, -b.z), fmaf(scale, acc.w, -b.w));
    } else {
        r = make_float4(scale*acc.x, scale*acc.y, scale*acc.z, scale*acc.w);
    }
    __stcs(&out[n*NV4 + idx], r);
}

// ---------------- fast activations ----------------
__device__ __forceinline__ float fast_sigmoid(float g) {
    return __fdividef(1.f, 1.f + __expf(-g));
}
__device__ __forceinline__ float fast_tanh(float x) {
    float t = __expf(-2.f * fabsf(x));
    float r = __fdividef(1.f - t, 1.f + t);
    return copysignf(r, x);
}

// ---------------- GEMM 1: gates ----------------
// G = sigmoid([X0 X1 X2] @ Wg^T + bg)  (M=320000, K=384, N=128)
// epilogue: z -> g_Z ;  g_RH = r*hx (compact, 64 feats)
__global__ __launch_bounds__(256, 2) void k_gates(const float* __restrict__ Wg,
                                                  const float* __restrict__ bg) {
    __shared__ __align__(16) float As[32][132];
    __shared__ __align__(16) float Bs[32][132];
    int tid = threadIdx.x;
    int tx = tid & 15;      // col group (8 cols = 4 pairs)
    int ty = tid >> 4;      // row group (8 rows)
    int m0 = blockIdx.x * 128;

    u64 acc2[8][4];
    #pragma unroll
    for (int i = 0; i < 8; i++)
        #pragma unroll
        for (int j = 0; j < 4; j++) acc2[i][j] = 0ULL;

    const float* bufs[3] = {g_X0, g_X1, g_X2};

    for (int bsel = 0; bsel < 3; bsel++) {
        const float* A = bufs[bsel];
        for (int kt = 0; kt < 128; kt += 32) {
            // A tile: 128 rows x 32 k (transposed store)
            #pragma unroll
            for (int j = 0; j < 4; j++) {
                int q = tid + 256*j;
                int r = q >> 3;
                int kk = (q & 7) << 2;
                float4 v = *(const float4*)&A[(m0 + r)*FF + kt + kk];
                As[kk+0][r] = v.x; As[kk+1][r] = v.y;
                As[kk+2][r] = v.z; As[kk+3][r] = v.w;
            }
            // B tile: Bs[k][n] = Wg[n][bsel*128 + kt + k]
            #pragma unroll
            for (int j = 0; j < 4; j++) {
                int q = tid + 256*j;
                int nn = q >> 3;
                int kk = (q & 7) << 2;
                float4 v = *(const float4*)&Wg[nn*384 + bsel*128 + kt + kk];
                Bs[kk+0][nn] = v.x; Bs[kk+1][nn] = v.y;
                Bs[kk+2][nn] = v.z; Bs[kk+3][nn] = v.w;
            }
            __syncthreads();
            #pragma unroll
            for (int kk = 0; kk < 32; kk++) {
                float4 a0 = *(const float4*)&As[kk][ty*8];
                float4 a1 = *(const float4*)&As[kk][ty*8 + 4];
                const u64* bp = (const u64*)&Bs[kk][tx*8];
                u64 b0 = bp[0], b1 = bp[1], b2 = bp[2], b3 = bp[3];
                float av[8] = {a0.x,a0.y,a0.z,a0.w,a1.x,a1.y,a1.z,a1.w};
                #pragma unroll
                for (int i = 0; i < 8; i++) {
                    u64 ai; PACK2(ai, __float_as_uint(av[i]));
                    FMA2(acc2[i][0], ai, b0);
                    FMA2(acc2[i][1], ai, b1);
                    FMA2(acc2[i][2], ai, b2);
                    FMA2(acc2[i][3], ai, b3);
                }
            }
            __syncthreads();
        }
    }

    // epilogue: z for c<64; RH = r*hx for c>=64
    #pragma unroll
    for (int i = 0; i < 8; i++) {
        int m = m0 + ty*8 + i;
        #pragma unroll
        for (int jj = 0; jj < 4; jj++) {
            unsigned lo, hi;
            UNPACK2(lo, hi, acc2[i][jj]);
            float vv[2] = {__uint_as_float(lo), __uint_as_float(hi)};
            #pragma unroll
            for (int h = 0; h < 2; h++) {
                int c = tx*8 + jj*2 + h;
                float s = fast_sigmoid(vv[h] + __ldg(&bg[c]));
                if (c < 64) {
                    g_Z[m*DOUT + c] = s;
                } else {
                    float hv = g_X0[m*FF + c];          // hx part
                    g_RH[m*DOUT + (c - 64)] = s * hv;
                }
            }
        }
    }
}

// ---------------- GEMM 2: candidate + final combine ----------------
// A-tiles: k<64 from {X0,X1,X2} (stride 128), k>=64 from {RH,D1,D2} (stride 64)
// cand = tanh(A @ Wc^T + bc) ; out = (1-z)*hx + z*cand  (N=64)
__global__ __launch_bounds__(256, 2) void k_cand(const float* __restrict__ Wc,
                                                 const float* __restrict__ bc,
                                                 float* __restrict__ out) {
    __shared__ __align__(16) float As[32][132];
    __shared__ __align__(16) float Bs[32][68];
    int tid = threadIdx.x;
    int tx = tid & 15;      // col group (4 cols = 2 pairs)
    int ty = tid >> 4;      // row group (8 rows)
    int m0 = blockIdx.x * 128;

    u64 acc2[8][2];
    #pragma unroll
    for (int i = 0; i < 8; i++) {
        acc2[i][0] = 0ULL; acc2[i][1] = 0ULL;
    }

    const float* xbufs[3] = {g_X0, g_X1, g_X2};
    const float* hbufs[3] = {g_RH, g_D1, g_D2};

    for (int bsel = 0; bsel < 3; bsel++) {
        for (int kt = 0; kt < 128; kt += 32) {
            const float* src;
            int stride, off;
            if (kt < 64) { src = xbufs[bsel]; stride = FF;   off = kt; }
            else         { src = hbufs[bsel]; stride = DOUT; off = kt - 64; }
            #pragma unroll
            for (int j = 0; j < 4; j++) {
                int q = tid + 256*j;
                int r = q >> 3;
                int kk = (q & 7) << 2;
                float4 v = *(const float4*)&src[(m0 + r)*stride + off + kk];
                As[kk+0][r] = v.x; As[kk+1][r] = v.y;
                As[kk+2][r] = v.z; As[kk+3][r] = v.w;
            }
            { // B tile: 64 rows x 32 k -> 512 float4, 2 per thread
                #pragma unroll
                for (int j = 0; j < 2; j++) {
                    int q = tid + 256*j;
                    int nn = q >> 3;
                    int kk = (q & 7) << 2;
                    float4 v = *(const float4*)&Wc[nn*384 + bsel*128 + kt + kk];
                    Bs[kk+0][nn] = v.x; Bs[kk+1][nn] = v.y;
                    Bs[kk+2][nn] = v.z; Bs[kk+3][nn] = v.w;
                }
            }
            __syncthreads();
            #pragma unroll
            for (int kk = 0; kk < 32; kk++) {
                float4 a0 = *(const float4*)&As[kk][ty*8];
                float4 a1 = *(const float4*)&As[kk][ty*8 + 4];
                const u64* bp = (const u64*)&Bs[kk][tx*4];
                u64 b0 = bp[0], b1 = bp[1];
                float av[8] = {a0.x,a0.y,a0.z,a0.w,a1.x,a1.y,a1.z,a1.w};
                #pragma unroll
                for (int i = 0; i < 8; i++) {
                    u64 ai; PACK2(ai, __float_as_uint(av[i]));
                    FMA2(acc2[i][0], ai, b0);
                    FMA2(acc2[i][1], ai, b1);
                }
            }
            __syncthreads();
        }
    }

    // epilogue: tanh, gate combine, write back in (B, N, 64) layout
    #pragma unroll
    for (int i = 0; i < 8; i++) {
        int m = m0 + ty*8 + i;
        int n = m >> 5;
        int b = m & 31;
        float* op = &out[b*(NN*DOUT) + n*DOUT + tx*4];
        float res[4];
        #pragma unroll
        for (int jj = 0; jj < 2; jj++) {
            unsigned lo, hi;
            UNPACK2(lo, hi, acc2[i][jj]);
            float vv[2] = {__uint_as_float(lo), __uint_as_float(hi)};
            #pragma unroll
            for (int h = 0; h < 2; h++) {
                int c = tx*4 + jj*2 + h;
                float cand = fast_tanh(vv[h] + __ldg(&bc[c]));
                float z  = g_Z[m*DOUT + c];
                float hv = g_X0[m*FF + 64 + c];
                res[jj*2 + h] = (1.f - z)*hv + z*cand;
            }
        }
        *(float4*)op = make_float4(res[0], res[1], res[2], res[3]);
    }
}

// ---------------- launch ----------------
extern "C" void kernel_launch(void* const* d_in, const int* in_sizes, int n_in,
                              void* d_out, int out_size) {
    // Resolve inputs by element count (robust to metadata ordering).
    const float* inp = nullptr;   // 20480000 (first occurrence)
    const float* hx  = nullptr;   // 20480000 (second occurrence)
    const void*  ei  = nullptr;   // 320000   (int32 or int64; detected on device)
    const float* ew  = nullptr;   // 160000
    const float* Wg  = nullptr;   // 49152
    const float* Wc  = nullptr;   // 24576
    const float* bg  = nullptr;   // 128
    const float* bc  = nullptr;   // 64
    for (int i = 0; i < n_in; i++) {
        switch (in_sizes[i]) {
            case 20480000: if (!inp) inp = (const float*)d_in[i];
                           else      hx  = (const float*)d_in[i]; break;
            case 320000:   ei = d_in[i];                 break;
            case 160000:   ew = (const float*)d_in[i];   break;
            case 49152:    Wg = (const float*)d_in[i];   break;
            case 24576:    Wc = (const float*)d_in[i];   break;
            case 128:      bg = (const float*)d_in[i];   break;
            case 64:       bc = (const float*)d_in[i];   break;
            default: break;
        }
    }
    float* out = (float*)d_out;

    void *pX0, *pX1, *pX2, *pRH, *pD1, *pD2;
    cudaGetSymbolAddress(&pX0, g_X0);
    cudaGetSymbolAddress(&pX1, g_X1);
    cudaGetSymbolAddress(&pX2, g_X2);
    cudaGetSymbolAddress(&pRH, g_RH);
    cudaGetSymbolAddress(&pD1, g_D1);
    cudaGetSymbolAddress(&pD2, g_D2);

    // CSR + X0 build (3 launches)
    k_zero_detect<<<40, 256>>>((const long long*)ei);
    k_histbuild<<<HIST_BLKS + NN, 256>>>(ei, inp, hx);
    k_scanfill<<<1, 1024>>>(ei, ew);

    // first diffusion (full width, 128 feats)
    dim3 gf(NN, 4);
    k_conv<V4F><<<gf, 256>>>((const float4*)pX0, nullptr,            (float4*)pX1, 1.f, 0);
    k_conv<V4F><<<gf, 256>>>((const float4*)pX1, (const float4*)pX0, (float4*)pX2, 2.f, 1);

    // gates GEMM (+ stores z, builds compact RH = r*hx)
    k_gates<<<MM/128, 256>>>(Wg, bg);

    // second diffusion on RH only (half width, 64 feats)
    dim3 gh(NN, 2);
    k_conv<V4H><<<gh, 256>>>((const float4*)pRH, nullptr,            (float4*)pD1, 1.f, 0);
    k_conv<V4H><<<gh, 256>>>((const float4*)pD1, (const float4*)pRH, (float4*)pD2, 2.f, 1);

    // candidate GEMM + tanh + gate combine + transpose to (B, N, 64)
    k_cand<<<MM/128, 256>>>(Wc, bc, out);
}

// round 7
// speedup vs baseline: 1.1601x; 1.1601x over previous
#include <cuda_runtime.h>
#include <math.h>

// Problem constants (fixed by the reference)
#define NN   10000            // nodes
#define NB   32               // batch
#define DIN  64
#define DOUT 64
#define FF   128              // DIN + DOUT
#define NE   160000           // edges
#define MM   (NN*NB)          // 320000 "rows" (node-major: m = n*32 + b)
#define BFLT (NB*FF)          // 4096 floats per node (full width)
#define V4F  (BFLT/4)         // 1024 float4 per node (full width)
#define V4H  (NB*DOUT/4)      // 512 float4 per node (half width)

typedef unsigned long long u64;

// packed 2xfp32 FMA (Blackwell FFMA2, PTX-only)
#define FMA2(d, a, b) asm("fma.rn.f32x2 %0, %1, %2, %0;" : "+l"(d) : "l"(a), "l"(b))
#define PACK2(d, f)   asm("mov.b64 %0, {%1, %1};" : "=l"(d) : "r"(f))
#define UNPACK2(lo, hi, d) asm("mov.b64 {%0, %1}, %2;" : "=r"(lo), "=r"(hi) : "l"(d))

// ---------------- scratch (device globals; allocation-free) ----------------
// g_X[s] : s=0 concat(inputs,hx) [n][b][128] ; s=1 A(x0) ; s=2 2A(x1)-x0
// g_H[s] : s=0 r*hx [n][b][64]  ; s=1 A(rh)  ; s=2 2A(h1)-rh
__device__ __align__(16) float g_X[3][(size_t)MM*FF];
__device__ __align__(16) float g_H[3][(size_t)MM*DOUT];
__device__ __align__(16) float g_Z[(size_t)MM*DOUT];   // update gate z
__device__ int    g_cnt[NN];
__device__ int    g_rs [NN+1];   // CSR row starts (by destination row)
__device__ int    g_cur[NN];
__device__ __align__(8) float2 g_epack[NE];   // {col as int bits, weight}

// ---------------- kernel 1: histogram (+dtype detect) / build X0 ----------------
// dtype detect per block: int64 view of first 256 entries all in [0,NN) iff data
// is int64 (int32 data packs two ids -> value >= NN unless hi==0, p~1e-4/elem).
#define HIST_BLKS (NE/256)     // 625
__global__ void k_histbuild(const long long* __restrict__ ei64,
                            const float* __restrict__ in,
                            const float* __restrict__ hx) {
    if (blockIdx.x < HIST_BLKS) {
        __shared__ int bad;
        if (threadIdx.x == 0) bad = 0;
        __syncthreads();
        long long v = ei64[threadIdx.x];
        if (v < 0 || v >= NN) atomicOr(&bad, 1);
        __syncthreads();
        int e = blockIdx.x*256 + threadIdx.x;
        int r;
        if (bad) r = ((const int*)ei64)[e];
        else     r = (int)ei64[e];
        atomicAdd(&g_cnt[r], 1);
    } else {
        int n = blockIdx.x - HIST_BLKS;
        for (int i = threadIdx.x; i < NB*DIN; i += 256) {
            int b = i >> 6, f = i & 63;
            g_X[0][(size_t)n*BFLT + b*FF + f]      = in[(size_t)b*(NN*DIN) + n*DIN + f];
            g_X[0][(size_t)n*BFLT + b*FF + 64 + f] = hx[(size_t)b*(NN*DOUT) + n*DOUT + f];
        }
    }
}

// ---------------- kernel 2: single-block scan + CSR fill + re-zero cnt ---------
__global__ void k_scanfill(const long long* __restrict__ ei64,
                           const float* __restrict__ ew) {
    __shared__ int sums[1024];
    __shared__ int bad;
    int t = threadIdx.x;
    if (t == 0) bad = 0;
    __syncthreads();
    if (t < 256) {
        long long v = ei64[t];
        if (v < 0 || v >= NN) atomicOr(&bad, 1);
    }
    const int CH = 10;                  // 1024*10 >= 10000
    int base = t*CH;
    int loc[CH];
    int s = 0;
    #pragma unroll
    for (int i = 0; i < CH; i++) {
        int idx = base + i;
        int v = (idx < NN) ? g_cnt[idx] : 0;
        loc[i] = s; s += v;
    }
    sums[t] = s;
    __syncthreads();
    for (int off = 1; off < 1024; off <<= 1) {
        int v = (t >= off) ? sums[t-off] : 0;
        __syncthreads();
        sums[t] += v;
        __syncthreads();
    }
    int prev = (t > 0) ? sums[t-1] : 0;
    #pragma unroll
    for (int i = 0; i < CH; i++) {
        int idx = base + i;
        if (idx < NN) {
            int v = prev + loc[i];
            g_rs[idx] = v;
            g_cur[idx] = v;
        }
    }
    if (t == 1023) g_rs[NN] = sums[1023];
    __syncthreads();
    // zero histogram for the NEXT call (graph replays the same sequence)
    for (int i = t; i < NN; i += 1024) g_cnt[i] = 0;
    // fill (atomic cursors)
    int is64 = !bad;
    for (int e = t; e < NE; e += 1024) {
        int r, c;
        if (is64) {
            r = (int)ei64[e];
            c = (int)ei64[NE + e];
        } else {
            r = ((const int*)ei64)[e];
            c = ((const int*)ei64)[NE + e];
        }
        int pos = atomicAdd(&g_cur[r], 1);
        g_epack[pos] = make_float2(__int_as_float(c), ew[e]);
    }
}

// ---------------- graph conv (CSR gather-reduce, feature-sliced) ----------------
// out[n] = scale * sum_{e in row n} w_e * x[col_e]  + (sub ? -base[n] : 0)
#define CONV_FMA(acc, p, v) \
    acc.x = fmaf(p.y, v.x, acc.x); acc.y = fmaf(p.y, v.y, acc.y); \
    acc.z = fmaf(p.y, v.z, acc.z); acc.w = fmaf(p.y, v.w, acc.w);

template<int NV4>
__global__ __launch_bounds__(256) void k_conv(const float4* __restrict__ x,
                       const float4* __restrict__ base,
                       float4* __restrict__ out,
                       float scale, int sub) {
    int n   = blockIdx.x;
    int idx = blockIdx.y*256 + threadIdx.x;     // float4 index within node
    const float4* xb = x + idx;
    float4 acc = make_float4(0.f, 0.f, 0.f, 0.f);
    int e0 = __ldg(&g_rs[n]);
    int e1 = __ldg(&g_rs[n+1]);
    int e = e0;
    for (; e + 4 <= e1; e += 4) {
        float2 p0 = __ldg(&g_epack[e]);
        float2 p1 = __ldg(&g_epack[e+1]);
        float2 p2 = __ldg(&g_epack[e+2]);
        float2 p3 = __ldg(&g_epack[e+3]);
        float4 v0 = __ldg(xb + __float_as_int(p0.x)*NV4);
        float4 v1 = __ldg(xb + __float_as_int(p1.x)*NV4);
        float4 v2 = __ldg(xb + __float_as_int(p2.x)*NV4);
        float4 v3 = __ldg(xb + __float_as_int(p3.x)*NV4);
        CONV_FMA(acc, p0, v0)
        CONV_FMA(acc, p1, v1)
        CONV_FMA(acc, p2, v2)
        CONV_FMA(acc, p3, v3)
    }
    for (; e < e1; e++) {
        float2 p0 = __ldg(&g_epack[e]);
        float4 v0 = __ldg(xb + __float_as_int(p0.x)*NV4);
        CONV_FMA(acc, p0, v0)
    }
    float4 r;
    if (sub) {
        float4 b = __ldg(&base[n*NV4 + idx]);
        r = make_float4(fmaf(scale, acc.x, -b.x), fmaf(scale, acc.y, -b.y),
                        fmaf(scale, acc.z, -b.z), fmaf(scale, acc.w, -b.w));
    } else {
        r = make_float4(scale*acc.x, scale*acc.y, scale*acc.z, scale*acc.w);
    }
    __stcs(&out[n*NV4 + idx], r);
}

// ---------------- fast activations ----------------
__device__ __forceinline__ float fast_sigmoid(float g) {
    return __fdividef(1.f, 1.f + __expf(-g));
}
__device__ __forceinline__ float fast_tanh(float x) {
    float t = __expf(-2.f * fabsf(x));
    float r = __fdividef(1.f - t, 1.f + t);
    return copysignf(r, x);
}

// ---------------- GEMM 1: gates ----------------
// G = sigmoid([X0 X1 X2] @ Wg^T + bg)  (M=320000, K=384, N=128)
// thread cols: pairs {2tx+32j, +1}, j=0..3 (conflict-free LDS.64 b-fetch)
// epilogue: z -> g_Z (c<64) ;  g_H[0] = r*hx (c>=64)
__global__ __launch_bounds__(256, 2) void k_gates(const float* __restrict__ Wg,
                                                  const float* __restrict__ bg) {
    __shared__ __align__(16) float As[32][132];
    __shared__ __align__(16) float Bs[32][132];
    int tid = threadIdx.x;
    int tx = tid & 15;
    int ty = tid >> 4;
    int m0 = blockIdx.x * 128;
    int lr = tid >> 3;            // load row base 0..31
    int lk = (tid & 7) << 2;      // load k offset 0..28

    u64 acc2[8][4];
    #pragma unroll
    for (int i = 0; i < 8; i++)
        #pragma unroll
        for (int j = 0; j < 4; j++) acc2[i][j] = 0ULL;

    const float* Xbase = (const float*)g_X;

    float4 ra[4], rb[4];
    // prologue: load tile 0
    {
        const float* A = Xbase;           // tt=0: bsel 0, kt 0
        #pragma unroll
        for (int j = 0; j < 4; j++)
            ra[j] = *(const float4*)&A[(size_t)(m0 + lr + 32*j)*FF + lk];
        #pragma unroll
        for (int j = 0; j < 4; j++)
            rb[j] = *(const float4*)&Wg[(lr + 32*j)*384 + lk];
    }

    #pragma unroll 1
    for (int tt = 0; tt < 12; tt++) {
        // store staged tile to smem (transposed)
        #pragma unroll
        for (int j = 0; j < 4; j++) {
            int r = lr + 32*j;
            As[lk+0][r] = ra[j].x; As[lk+1][r] = ra[j].y;
            As[lk+2][r] = ra[j].z; As[lk+3][r] = ra[j].w;
            Bs[lk+0][r] = rb[j].x; Bs[lk+1][r] = rb[j].y;
            Bs[lk+2][r] = rb[j].z; Bs[lk+3][r] = rb[j].w;
        }
        __syncthreads();
        // prefetch next tile
        if (tt < 11) {
            int nt = tt + 1;
            const float* A = Xbase + (size_t)(nt >> 2)*((size_t)MM*FF);
            int kt = (nt & 3)*32;
            #pragma unroll
            for (int j = 0; j < 4; j++)
                ra[j] = *(const float4*)&A[(size_t)(m0 + lr + 32*j)*FF + kt + lk];
            int wo = (nt >> 2)*128 + kt;
            #pragma unroll
            for (int j = 0; j < 4; j++)
                rb[j] = *(const float4*)&Wg[(lr + 32*j)*384 + wo + lk];
        }
        // compute
        #pragma unroll
        for (int kk = 0; kk < 32; kk++) {
            float4 a0 = *(const float4*)&As[kk][ty*8];
            float4 a1 = *(const float4*)&As[kk][ty*8 + 4];
            u64 b0 = *(const u64*)&Bs[kk][2*tx];
            u64 b1 = *(const u64*)&Bs[kk][2*tx + 32];
            u64 b2 = *(const u64*)&Bs[kk][2*tx + 64];
            u64 b3 = *(const u64*)&Bs[kk][2*tx + 96];
            float av[8] = {a0.x,a0.y,a0.z,a0.w,a1.x,a1.y,a1.z,a1.w};
            #pragma unroll
            for (int i = 0; i < 8; i++) {
                u64 ai; PACK2(ai, __float_as_uint(av[i]));
                FMA2(acc2[i][0], ai, b0);
                FMA2(acc2[i][1], ai, b1);
                FMA2(acc2[i][2], ai, b2);
                FMA2(acc2[i][3], ai, b3);
            }
        }
        __syncthreads();
    }

    // epilogue: j=0,1 -> z (c<64) ; j=2,3 -> RH = r*hx (c>=64)
    #pragma unroll
    for (int i = 0; i < 8; i++) {
        size_t m = (size_t)(m0 + ty*8 + i);
        #pragma unroll
        for (int j = 0; j < 4; j++) {
            int c0 = 2*tx + 32*j;
            unsigned lo, hi;
            UNPACK2(lo, hi, acc2[i][j]);
            float s0 = fast_sigmoid(__uint_as_float(lo) + __ldg(&bg[c0]));
            float s1 = fast_sigmoid(__uint_as_float(hi) + __ldg(&bg[c0+1]));
            if (j < 2) {
                *(float2*)&g_Z[m*DOUT + c0] = make_float2(s0, s1);
            } else {
                float2 hv = *(const float2*)&g_X[0][m*FF + c0];   // c0 in [64,127)
                *(float2*)&g_H[0][m*DOUT + (c0 - 64)] =
                    make_float2(s0*hv.x, s1*hv.y);
            }
        }
    }
}

// ---------------- GEMM 2: candidate + final combine ----------------
// A-tiles: kt<64 from g_X[bsel] (stride 128), kt>=64 from g_H[bsel] (stride 64)
// cand = tanh(A @ Wc^T + bc) ; out = (1-z)*hx + z*cand  (N=64)
__global__ __launch_bounds__(256, 2) void k_cand(const float* __restrict__ Wc,
                                                 const float* __restrict__ bc,
                                                 float* __restrict__ out) {
    __shared__ __align__(16) float As[32][132];
    __shared__ __align__(16) float Bs[32][68];
    int tid = threadIdx.x;
    int tx = tid & 15;
    int ty = tid >> 4;
    int m0 = blockIdx.x * 128;
    int lr = tid >> 3;
    int lk = (tid & 7) << 2;

    u64 acc2[8][2];
    #pragma unroll
    for (int i = 0; i < 8; i++) { acc2[i][0] = 0ULL; acc2[i][1] = 0ULL; }

    const float* Xbase = (const float*)g_X;
    const float* Hbase = (const float*)g_H;

    float4 ra[4], rb[2];
    {   // tile 0: bsel 0, kt 0 -> X side
        #pragma unroll
        for (int j = 0; j < 4; j++)
            ra[j] = *(const float4*)&Xbase[(size_t)(m0 + lr + 32*j)*FF + lk];
        #pragma unroll
        for (int j = 0; j < 2; j++)
            rb[j] = *(const float4*)&Wc[(lr + 32*j)*384 + lk];
    }

    #pragma unroll 1
    for (int tt = 0; tt < 12; tt++) {
        #pragma unroll
        for (int j = 0; j < 4; j++) {
            int r = lr + 32*j;
            As[lk+0][r] = ra[j].x; As[lk+1][r] = ra[j].y;
            As[lk+2][r] = ra[j].z; As[lk+3][r] = ra[j].w;
        }
        #pragma unroll
        for (int j = 0; j < 2; j++) {
            int r = lr + 32*j;
            Bs[lk+0][r] = rb[j].x; Bs[lk+1][r] = rb[j].y;
            Bs[lk+2][r] = rb[j].z; Bs[lk+3][r] = rb[j].w;
        }
        __syncthreads();
        if (tt < 11) {
            int nt = tt + 1;
            if (nt & 2) {   // H side: stride 64, off (nt&1)*32
                const float* A = Hbase + (size_t)(nt >> 2)*((size_t)MM*DOUT);
                int off = (nt & 1)*32;
                #pragma unroll
                for (int j = 0; j < 4; j++)
                    ra[j] = *(const float4*)&A[(size_t)(m0 + lr + 32*j)*DOUT + off + lk];
            } else {        // X side: stride 128, off (nt&1)*32
                const float* A = Xbase + (size_t)(nt >> 2)*((size_t)MM*FF);
                int off = (nt & 1)*32;
                #pragma unroll
                for (int j = 0; j < 4; j++)
                    ra[j] = *(const float4*)&A[(size_t)(m0 + lr + 32*j)*FF + off + lk];
            }
            int wo = (nt >> 2)*128 + (nt & 3)*32;
            #pragma unroll
            for (int j = 0; j < 2; j++)
                rb[j] = *(const float4*)&Wc[(lr + 32*j)*384 + wo + lk];
        }
        #pragma unroll
        for (int kk = 0; kk < 32; kk++) {
            float4 a0 = *(const float4*)&As[kk][ty*8];
            float4 a1 = *(const float4*)&As[kk][ty*8 + 4];
            u64 b0 = *(const u64*)&Bs[kk][2*tx];
            u64 b1 = *(const u64*)&Bs[kk][2*tx + 32];
            float av[8] = {a0.x,a0.y,a0.z,a0.w,a1.x,a1.y,a1.z,a1.w};
            #pragma unroll
            for (int i = 0; i < 8; i++) {
                u64 ai; PACK2(ai, __float_as_uint(av[i]));
                FMA2(acc2[i][0], ai, b0);
                FMA2(acc2[i][1], ai, b1);
            }
        }
        __syncthreads();
    }

    // epilogue: tanh, gate combine, write back in (B, N, 64) layout
    #pragma unroll
    for (int i = 0; i < 8; i++) {
        size_t m = (size_t)(m0 + ty*8 + i);
        int n = (int)(m >> 5);
        int b = (int)(m & 31);
        #pragma unroll
        for (int j = 0; j < 2; j++) {
            int c0 = 2*tx + 32*j;
            unsigned lo, hi;
            UNPACK2(lo, hi, acc2[i][j]);
            float cand0 = fast_tanh(__uint_as_float(lo) + __ldg(&bc[c0]));
            float cand1 = fast_tanh(__uint_as_float(hi) + __ldg(&bc[c0+1]));
            float2 z2 = *(const float2*)&g_Z[m*DOUT + c0];
            float2 h2 = *(const float2*)&g_X[0][m*FF + 64 + c0];
            float2 r2 = make_float2((1.f - z2.x)*h2.x + z2.x*cand0,
                                    (1.f - z2.y)*h2.y + z2.y*cand1);
            *(float2*)&out[(size_t)b*(NN*DOUT) + (size_t)n*DOUT + c0] = r2;
        }
    }
}

// ---------------- launch ----------------
extern "C" void kernel_launch(void* const* d_in, const int* in_sizes, int n_in,
                              void* d_out, int out_size) {
    // Resolve inputs by element count (robust to metadata ordering).
    const float* inp = nullptr;   // 20480000 (first occurrence)
    const float* hx  = nullptr;   // 20480000 (second occurrence)
    const void*  ei  = nullptr;   // 320000   (int32 or int64; detected on device)
    const float* ew  = nullptr;   // 160000
    const float* Wg  = nullptr;   // 49152
    const float* Wc  = nullptr;   // 24576
    const float* bg  = nullptr;   // 128
    const float* bc  = nullptr;   // 64
    for (int i = 0; i < n_in; i++) {
        switch (in_sizes[i]) {
            case 20480000: if (!inp) inp = (const float*)d_in[i];
                           else      hx  = (const float*)d_in[i]; break;
            case 320000:   ei = d_in[i];                 break;
            case 160000:   ew = (const float*)d_in[i];   break;
            case 49152:    Wg = (const float*)d_in[i];   break;
            case 24576:    Wc = (const float*)d_in[i];   break;
            case 128:      bg = (const float*)d_in[i];   break;
            case 64:       bc = (const float*)d_in[i];   break;
            default: break;
        }
    }
    float* out = (float*)d_out;

    void *pX, *pH;
    cudaGetSymbolAddress(&pX, g_X);
    cudaGetSymbolAddress(&pH, g_H);
    float* X = (float*)pX;
    float* H = (float*)pH;
    const size_t XS = (size_t)MM*FF;
    const size_t HS = (size_t)MM*DOUT;

    // 1-2: CSR + X0 build (g_cnt zeroed by previous call / module init)
    k_histbuild<<<HIST_BLKS + NN, 256>>>((const long long*)ei, inp, hx);
    k_scanfill<<<1, 1024>>>((const long long*)ei, ew);

    // 3-4: first diffusion (full width, 128 feats)
    dim3 gf(NN, 4);
    k_conv<V4F><<<gf, 256>>>((const float4*)X,        nullptr,
                             (float4*)(X + XS),       1.f, 0);
    k_conv<V4F><<<gf, 256>>>((const float4*)(X + XS), (const float4*)X,
                             (float4*)(X + 2*XS),     2.f, 1);

    // 5: gates GEMM (+ stores z, builds compact RH = r*hx)
    k_gates<<<MM/128, 256>>>(Wg, bg);

    // 6-7: second diffusion on RH only (half width, 64 feats)
    dim3 gh(NN, 2);
    k_conv<V4H><<<gh, 256>>>((const float4*)H,        nullptr,
                             (float4*)(H + HS),       1.f, 0);
    k_conv<V4H><<<gh, 256>>>((const float4*)(H + HS), (const float4*)H,
                             (float4*)(H + 2*HS),     2.f, 1);

    // 8: candidate GEMM + tanh + gate combine + transpose to (B, N, 64)
    k_cand<<<MM/128, 256>>>(Wc, bc, out);
}

// round 10
// speedup vs baseline: 1.6497x; 1.4220x over previous
#include <cuda_runtime.h>
#include <cuda_bf16.h>
#include <math.h>
#include <stdint.h>

// Problem constants (fixed by the reference)
#define NN   10000            // nodes
#define NB   32               // batch
#define DIN  64
#define DOUT 64
#define FF   128              // DIN + DOUT
#define NE   160000           // edges
#define MM   (NN*NB)          // 320000 rows (node-major: m = n*32 + b)
#define BFLT (NB*FF)          // 4096 floats per node (full width)
#define V4F  (BFLT/4)         // 1024 float4 per node (full width)
#define V4H  (NB*DOUT/4)      // 512 float4 per node (half width)

typedef unsigned long long u64;
typedef unsigned int u32;

// ---------------- scratch (device globals; allocation-free) ----------------
__device__ __align__(16) float g_X[3][(size_t)MM*FF];   // X0, X1, X2
__device__ __align__(16) float g_H[3][(size_t)MM*DOUT]; // RH, D1, D2
__device__ __align__(16) float g_Z[(size_t)MM*DOUT];    // update gate z
__device__ int    g_cnt[NN];
__device__ int    g_rs [NN+1];
__device__ int    g_cur[NN];
__device__ __align__(8) float2 g_epack[NE];   // {col as int bits, weight}

// ---------------- bf16 hi/lo split helpers ----------------
__device__ __forceinline__ unsigned packhi2(float a, float b, float& ra, float& rb) {
    __nv_bfloat16 ha = __float2bfloat16(a), hb = __float2bfloat16(b);
    ra = a - __bfloat162float(ha);
    rb = b - __bfloat162float(hb);
    __nv_bfloat162 t = __halves2bfloat162(ha, hb);
    return *reinterpret_cast<unsigned*>(&t);
}
__device__ __forceinline__ unsigned packlo2(float a, float b) {
    __nv_bfloat162 t = __floats2bfloat162_rn(a, b);
    return *reinterpret_cast<unsigned*>(&t);
}
// split float4 (4 k-values) -> 8 bytes per plane at byte offset `off`
__device__ __forceinline__ void split_store_plane(float4 v, char* hi, char* lo, int off) {
    float r0, r1, r2, r3;
    unsigned h0 = packhi2(v.x, v.y, r0, r1);
    unsigned h1 = packhi2(v.z, v.w, r2, r3);
    *(uint2*)(hi + off) = make_uint2(h0, h1);
    *(uint2*)(lo + off) = make_uint2(packlo2(r0, r1), packlo2(r2, r3));
}

// mma.sync m16n8k16 row.col f32.bf16.bf16.f32 (family PTX, sm_80+)
__device__ __forceinline__ void mma_bf16(float* c,
        u32 a0, u32 a1, u32 a2, u32 a3, u32 b0, u32 b1) {
    asm volatile("mma.sync.aligned.m16n8k16.row.col.f32.bf16.bf16.f32 "
        "{%0,%1,%2,%3}, {%4,%5,%6,%7}, {%8,%9}, {%0,%1,%2,%3};"
        : "+f"(c[0]), "+f"(c[1]), "+f"(c[2]), "+f"(c[3])
        : "r"(a0), "r"(a1), "r"(a2), "r"(a3), "r"(b0), "r"(b1));
}

// ---------------- fast activations ----------------
__device__ __forceinline__ float fast_sigmoid(float g) {
    return __fdividef(1.f, 1.f + __expf(-g));
}
__device__ __forceinline__ float fast_tanh(float x) {
    float t = __expf(-2.f * fabsf(x));
    float r = __fdividef(1.f - t, 1.f + t);
    return copysignf(r, x);
}

// ---------------- kernel 1: histogram (+dtype detect) / build X0 ----------------
#define HIST_BLKS (NE/256)     // 625
__global__ void k_histbuild(const long long* __restrict__ ei64,
                            const float* __restrict__ in,
                            const float* __restrict__ hx) {
    if (blockIdx.x < HIST_BLKS) {
        __shared__ int bad;
        if (threadIdx.x == 0) bad = 0;
        __syncthreads();
        long long v = ei64[threadIdx.x];
        if (v < 0 || v >= NN) atomicOr(&bad, 1);
        __syncthreads();
        int e = blockIdx.x*256 + threadIdx.x;
        int r;
        if (bad) r = ((const int*)ei64)[e];
        else     r = (int)ei64[e];
        atomicAdd(&g_cnt[r], 1);
    } else {
        int n = blockIdx.x - HIST_BLKS;
        for (int i = threadIdx.x; i < NB*DIN; i += 256) {
            int b = i >> 6, f = i & 63;
            g_X[0][(size_t)n*BFLT + b*FF + f]      = in[(size_t)b*(NN*DIN) + n*DIN + f];
            g_X[0][(size_t)n*BFLT + b*FF + 64 + f] = hx[(size_t)b*(NN*DOUT) + n*DOUT + f];
        }
    }
}

// ---------------- kernel 2: single-block scan + CSR fill + re-zero cnt ---------
__global__ void k_scanfill(const long long* __restrict__ ei64,
                           const float* __restrict__ ew) {
    __shared__ int sums[1024];
    __shared__ int bad;
    int t = threadIdx.x;
    if (t == 0) bad = 0;
    __syncthreads();
    if (t < 256) {
        long long v = ei64[t];
        if (v < 0 || v >= NN) atomicOr(&bad, 1);
    }
    const int CH = 10;
    int base = t*CH;
    int loc[CH];
    int s = 0;
    #pragma unroll
    for (int i = 0; i < CH; i++) {
        int idx = base + i;
        int v = (idx < NN) ? g_cnt[idx] : 0;
        loc[i] = s; s += v;
    }
    sums[t] = s;
    __syncthreads();
    for (int off = 1; off < 1024; off <<= 1) {
        int v = (t >= off) ? sums[t-off] : 0;
        __syncthreads();
        sums[t] += v;
        __syncthreads();
    }
    int prev = (t > 0) ? sums[t-1] : 0;
    #pragma unroll
    for (int i = 0; i < CH; i++) {
        int idx = base + i;
        if (idx < NN) {
            int v = prev + loc[i];
            g_rs[idx] = v;
            g_cur[idx] = v;
        }
    }
    if (t == 1023) g_rs[NN] = sums[1023];
    __syncthreads();
    for (int i = t; i < NN; i += 1024) g_cnt[i] = 0;   // for next replay
    int is64 = !bad;
    for (int e = t; e < NE; e += 1024) {
        int r, c;
        if (is64) {
            r = (int)ei64[e];
            c = (int)ei64[NE + e];
        } else {
            r = ((const int*)ei64)[e];
            c = ((const int*)ei64)[NE + e];
        }
        int pos = atomicAdd(&g_cur[r], 1);
        g_epack[pos] = make_float2(__int_as_float(c), ew[e]);
    }
}

// ---------------- graph conv (CSR gather-reduce, feature-sliced, 2-edge) -------
#define CONV_FMA(acc, p, v) \
    acc.x = fmaf(p.y, v.x, acc.x); acc.y = fmaf(p.y, v.y, acc.y); \
    acc.z = fmaf(p.y, v.z, acc.z); acc.w = fmaf(p.y, v.w, acc.w);

template<int NV4>
__global__ __launch_bounds__(256) void k_conv(const float4* __restrict__ x,
                       const float4* __restrict__ base,
                       float4* __restrict__ out,
                       float scale, int sub) {
    int n   = blockIdx.x;
    int idx = blockIdx.y*256 + threadIdx.x;
    const float4* xb = x + idx;
    float4 acc = make_float4(0.f, 0.f, 0.f, 0.f);
    int e0 = __ldg(&g_rs[n]);
    int e1 = __ldg(&g_rs[n+1]);
    int e = e0;
    for (; e + 2 <= e1; e += 2) {
        float2 p0 = __ldg(&g_epack[e]);
        float2 p1 = __ldg(&g_epack[e+1]);
        float4 v0 = __ldg(xb + __float_as_int(p0.x)*NV4);
        float4 v1 = __ldg(xb + __float_as_int(p1.x)*NV4);
        CONV_FMA(acc, p0, v0)
        CONV_FMA(acc, p1, v1)
    }
    if (e < e1) {
        float2 p0 = __ldg(&g_epack[e]);
        float4 v0 = __ldg(xb + __float_as_int(p0.x)*NV4);
        CONV_FMA(acc, p0, v0)
    }
    float4 r;
    if (sub) {
        float4 b = __ldg(&base[n*NV4 + idx]);
        r = make_float4(fmaf(scale, acc.x, -b.x), fmaf(scale, acc.y, -b.y),
                        fmaf(scale, acc.z, -b.z), fmaf(scale, acc.w, -b.w));
    } else {
        r = make_float4(scale*acc.x, scale*acc.y, scale*acc.z, scale*acc.w);
    }
    __stcs(&out[n*NV4 + idx], r);
}

// ================= GEMM 1: gates via mma.sync bf16-split =================
// D[128 x 128] += [X0 X1 X2](m0..m0+128, K=384) @ Wg^T ; 6 chunks of K=64
// smem planes: 128 rows x 144 B pitch (64 bf16 = 128 B data + 16 pad)
//   AHI 0, ALO 18432, BHI 36864, BLO 55296 ; total 73728
// warps: rb = wid&3 (32 rows), cb = wid>>2 (64 cols: cb0 -> z, cb1 -> r*hx)
extern __shared__ char dynsm[];

__global__ __launch_bounds__(256, 2)
void k_gates_mma(const float* __restrict__ Wg, const float* __restrict__ bg) {
    char* AHI = dynsm;
    char* ALO = dynsm + 18432;
    char* BHI = dynsm + 36864;
    char* BLO = dynsm + 55296;
    int tid = threadIdx.x, wid = tid >> 5, lid = tid & 31;
    int g = lid >> 2, t = lid & 3;
    int m0 = blockIdx.x * 128;
    int rb = wid & 3, cb = wid >> 2;

    float acc[2][8][4];
    #pragma unroll
    for (int i = 0; i < 2; i++)
        #pragma unroll
        for (int j = 0; j < 8; j++)
            #pragma unroll
            for (int k = 0; k < 4; k++) acc[i][j][k] = 0.f;

    const float* Xflat = (const float*)g_X;
    const size_t XS = (size_t)MM*FF;

    #pragma unroll 1
    for (int c = 0; c < 6; c++) {
        const float* Asrc = Xflat + (size_t)(c >> 1)*XS + (c & 1)*64;
        #pragma unroll
        for (int i = 0; i < 8; i++) {
            int f = tid + 256*i;            // float4 id 0..2047
            int r = f >> 4, c4 = f & 15;    // 16 float4 per row (64 k)
            float4 v = __ldg((const float4*)&Asrc[(size_t)(m0 + r)*FF + c4*4]);
            split_store_plane(v, AHI, ALO, r*144 + c4*8);
        }
        #pragma unroll
        for (int i = 0; i < 8; i++) {
            int f = tid + 256*i;
            int r = f >> 4, c4 = f & 15;
            float4 v = __ldg((const float4*)&Wg[r*384 + c*64 + c4*4]);
            split_store_plane(v, BHI, BLO, r*144 + c4*8);
        }
        __syncthreads();
        #pragma unroll
        for (int ks = 0; ks < 4; ks++) {
            int abase = (rb*32 + g)*144 + (ks*8 + t)*4;
            u32 ah[8], al[8];
            #pragma unroll
            for (int ma = 0; ma < 2; ma++) {
                int ro = abase + ma*2304;       // +16 rows
                ah[ma*4+0] = *(const u32*)(AHI + ro);
                ah[ma*4+1] = *(const u32*)(AHI + ro + 1152);   // +8 rows
                ah[ma*4+2] = *(const u32*)(AHI + ro + 16);     // k+8
                ah[ma*4+3] = *(const u32*)(AHI + ro + 1152 + 16);
                al[ma*4+0] = *(const u32*)(ALO + ro);
                al[ma*4+1] = *(const u32*)(ALO + ro + 1152);
                al[ma*4+2] = *(const u32*)(ALO + ro + 16);
                al[ma*4+3] = *(const u32*)(ALO + ro + 1152 + 16);
            }
            #pragma unroll
            for (int na = 0; na < 8; na++) {
                int bbase = (cb*64 + na*8 + g)*144 + (ks*8 + t)*4;
                u32 bh0 = *(const u32*)(BHI + bbase);
                u32 bh1 = *(const u32*)(BHI + bbase + 16);
                u32 bl0 = *(const u32*)(BLO + bbase);
                u32 bl1 = *(const u32*)(BLO + bbase + 16);
                mma_bf16(acc[0][na], ah[0], ah[1], ah[2], ah[3], bh0, bh1);
                mma_bf16(acc[1][na], ah[4], ah[5], ah[6], ah[7], bh0, bh1);
                mma_bf16(acc[0][na], ah[0], ah[1], ah[2], ah[3], bl0, bl1);
                mma_bf16(acc[1][na], ah[4], ah[5], ah[6], ah[7], bl0, bl1);
                mma_bf16(acc[0][na], al[0], al[1], al[2], al[3], bh0, bh1);
                mma_bf16(acc[1][na], al[4], al[5], al[6], al[7], bh0, bh1);
            }
        }
        __syncthreads();
    }

    // epilogue: sigmoid; cb==0 -> z ; cb==1 -> RH = r*hx (compact)
    #pragma unroll
    for (int ma = 0; ma < 2; ma++) {
        #pragma unroll
        for (int gg = 0; gg < 2; gg++) {
            size_t m = (size_t)(m0 + rb*32 + ma*16 + g + gg*8);
            #pragma unroll
            for (int na = 0; na < 8; na++) {
                int col = cb*64 + na*8 + 2*t;
                float s0 = fast_sigmoid(acc[ma][na][2*gg+0] + __ldg(&bg[col]));
                float s1 = fast_sigmoid(acc[ma][na][2*gg+1] + __ldg(&bg[col+1]));
                if (cb == 0) {
                    *(float2*)&g_Z[m*DOUT + col] = make_float2(s0, s1);
                } else {
                    int cc = col - 64;
                    float2 hv = *(const float2*)&g_X[0][m*FF + 64 + cc];
                    *(float2*)&g_H[0][m*DOUT + cc] = make_float2(s0*hv.x, s1*hv.y);
                }
            }
        }
    }
}

// ================= GEMM 2: candidate via mma.sync bf16-split + combine ========
// A chunks: even c -> g_X[c>>1] first 64 cols (stride 128); odd -> g_H[c>>1] (stride 64)
// smem: AHI 0, ALO 18432, BHI 36864 (64x144), BLO 46080 ; total 55296
__global__ __launch_bounds__(256, 2)
void k_cand_mma(const float* __restrict__ Wc, const float* __restrict__ bc,
                float* __restrict__ out) {
    char* AHI = dynsm;
    char* ALO = dynsm + 18432;
    char* BHI = dynsm + 36864;
    char* BLO = dynsm + 46080;
    int tid = threadIdx.x, wid = tid >> 5, lid = tid & 31;
    int g = lid >> 2, t = lid & 3;
    int m0 = blockIdx.x * 128;
    int rb = wid & 3, cb = wid >> 2;    // cols: cb*32

    float acc[2][4][4];
    #pragma unroll
    for (int i = 0; i < 2; i++)
        #pragma unroll
        for (int j = 0; j < 4; j++)
            #pragma unroll
            for (int k = 0; k < 4; k++) acc[i][j][k] = 0.f;

    const float* Xflat = (const float*)g_X;
    const float* Hflat = (const float*)g_H;
    const size_t XS = (size_t)MM*FF;
    const size_t HS = (size_t)MM*DOUT;

    #pragma unroll 1
    for (int c = 0; c < 6; c++) {
        const float* Asrc;
        int stride;
        if ((c & 1) == 0) { Asrc = Xflat + (size_t)(c >> 1)*XS; stride = FF; }
        else              { Asrc = Hflat + (size_t)(c >> 1)*HS; stride = DOUT; }
        #pragma unroll
        for (int i = 0; i < 8; i++) {
            int f = tid + 256*i;
            int r = f >> 4, c4 = f & 15;
            float4 v = __ldg((const float4*)&Asrc[(size_t)(m0 + r)*stride + c4*4]);
            split_store_plane(v, AHI, ALO, r*144 + c4*8);
        }
        #pragma unroll
        for (int i = 0; i < 4; i++) {       // B: 64 rows x 64 k
            int f = tid + 256*i;
            int r = f >> 4, c4 = f & 15;
            float4 v = __ldg((const float4*)&Wc[r*384 + c*64 + c4*4]);
            split_store_plane(v, BHI, BLO, r*144 + c4*8);
        }
        __syncthreads();
        #pragma unroll
        for (int ks = 0; ks < 4; ks++) {
            int abase = (rb*32 + g)*144 + (ks*8 + t)*4;
            u32 ah[8], al[8];
            #pragma unroll
            for (int ma = 0; ma < 2; ma++) {
                int ro = abase + ma*2304;
                ah[ma*4+0] = *(const u32*)(AHI + ro);
                ah[ma*4+1] = *(const u32*)(AHI + ro + 1152);
                ah[ma*4+2] = *(const u32*)(AHI + ro + 16);
                ah[ma*4+3] = *(const u32*)(AHI + ro + 1152 + 16);
                al[ma*4+0] = *(const u32*)(ALO + ro);
                al[ma*4+1] = *(const u32*)(ALO + ro + 1152);
                al[ma*4+2] = *(const u32*)(ALO + ro + 16);
                al[ma*4+3] = *(const u32*)(ALO + ro + 1152 + 16);
            }
            #pragma unroll
            for (int na = 0; na < 4; na++) {
                int bbase = (cb*32 + na*8 + g)*144 + (ks*8 + t)*4;
                u32 bh0 = *(const u32*)(BHI + bbase);
                u32 bh1 = *(const u32*)(BHI + bbase + 16);
                u32 bl0 = *(const u32*)(BLO + bbase);
                u32 bl1 = *(const u32*)(BLO + bbase + 16);
                mma_bf16(acc[0][na], ah[0], ah[1], ah[2], ah[3], bh0, bh1);
                mma_bf16(acc[1][na], ah[4], ah[5], ah[6], ah[7], bh0, bh1);
                mma_bf16(acc[0][na], ah[0], ah[1], ah[2], ah[3], bl0, bl1);
                mma_bf16(acc[1][na], ah[4], ah[5], ah[6], ah[7], bl0, bl1);
                mma_bf16(acc[0][na], al[0], al[1], al[2], al[3], bh0, bh1);
                mma_bf16(acc[1][na], al[4], al[5], al[6], al[7], bh0, bh1);
            }
        }
        __syncthreads();
    }

    // epilogue: tanh, gate combine, write (B, N, 64) layout
    #pragma unroll
    for (int ma = 0; ma < 2; ma++) {
        #pragma unroll
        for (int gg = 0; gg < 2; gg++) {
            size_t m = (size_t)(m0 + rb*32 + ma*16 + g + gg*8);
            int n = (int)(m >> 5);
            int b = (int)(m & 31);
            #pragma unroll
            for (int na = 0; na < 4; na++) {
                int col = cb*32 + na*8 + 2*t;
                float cd0 = fast_tanh(acc[ma][na][2*gg+0] + __ldg(&bc[col]));
                float cd1 = fast_tanh(acc[ma][na][2*gg+1] + __ldg(&bc[col+1]));
                float2 z2 = *(const float2*)&g_Z[m*DOUT + col];
                float2 h2 = *(const float2*)&g_X[0][m*FF + 64 + col];
                float2 r2 = make_float2((1.f - z2.x)*h2.x + z2.x*cd0,
                                        (1.f - z2.y)*h2.y + z2.y*cd1);
                *(float2*)&out[(size_t)b*(NN*DOUT) + (size_t)n*DOUT + col] = r2;
            }
        }
    }
}

// ---------------- launch ----------------
extern "C" void kernel_launch(void* const* d_in, const int* in_sizes, int n_in,
                              void* d_out, int out_size) {
    const float* inp = nullptr;
    const float* hx  = nullptr;
    const void*  ei  = nullptr;
    const float* ew  = nullptr;
    const float* Wg  = nullptr;
    const float* Wc  = nullptr;
    const float* bg  = nullptr;
    const float* bc  = nullptr;
    for (int i = 0; i < n_in; i++) {
        switch (in_sizes[i]) {
            case 20480000: if (!inp) inp = (const float*)d_in[i];
                           else      hx  = (const float*)d_in[i]; break;
            case 320000:   ei = d_in[i];                 break;
            case 160000:   ew = (const float*)d_in[i];   break;
            case 49152:    Wg = (const float*)d_in[i];   break;
            case 24576:    Wc = (const float*)d_in[i];   break;
            case 128:      bg = (const float*)d_in[i];   break;
            case 64:       bc = (const float*)d_in[i];   break;
            default: break;
        }
    }
    float* out = (float*)d_out;

    void *pX, *pH;
    cudaGetSymbolAddress(&pX, g_X);
    cudaGetSymbolAddress(&pH, g_H);
    float* X = (float*)pX;
    float* H = (float*)pH;
    const size_t XS = (size_t)MM*FF;
    const size_t HS = (size_t)MM*DOUT;

    cudaFuncSetAttribute(k_gates_mma, cudaFuncAttributeMaxDynamicSharedMemorySize, 73728);
    cudaFuncSetAttribute(k_cand_mma,  cudaFuncAttributeMaxDynamicSharedMemorySize, 55296);

    // 1-2: CSR + X0 build
    k_histbuild<<<HIST_BLKS + NN, 256>>>((const long long*)ei, inp, hx);
    k_scanfill<<<1, 1024>>>((const long long*)ei, ew);

    // 3-4: first diffusion (full width, 128 feats)
    dim3 gf(NN, 4);
    k_conv<V4F><<<gf, 256>>>((const float4*)X,        nullptr,
                             (float4*)(X + XS),       1.f, 0);
    k_conv<V4F><<<gf, 256>>>((const float4*)(X + XS), (const float4*)X,
                             (float4*)(X + 2*XS),     2.f, 1);

    // 5: gates GEMM (tensor cores via mma.sync) -> z, RH
    k_gates_mma<<<MM/128, 256, 73728>>>(Wg, bg);

    // 6-7: second diffusion on RH (half width)
    dim3 gh(NN, 2);
    k_conv<V4H><<<gh, 256>>>((const float4*)H,        nullptr,
                             (float4*)(H + HS),       1.f, 0);
    k_conv<V4H><<<gh, 256>>>((const float4*)(H + HS), (const float4*)H,
                             (float4*)(H + 2*HS),     2.f, 1);

    // 8: candidate GEMM (tensor cores) + combine + transpose
    k_cand_mma<<<MM/128, 256, 55296>>>(Wc, bc, out);
}

// round 11
// speedup vs baseline: 1.6615x; 1.0072x over previous
#include <cuda_runtime.h>
#include <cuda_bf16.h>
#include <math.h>
#include <stdint.h>

// Problem constants (fixed by the reference)
#define NN   10000            // nodes
#define NB   32               // batch
#define DIN  64
#define DOUT 64
#define FF   128              // DIN + DOUT
#define NE   160000           // edges
#define MM   (NN*NB)          // 320000 rows (node-major: m = n*32 + b)
#define BFLT (NB*FF)          // 4096 floats per node (full width)
#define V4F  (BFLT/4)         // 1024 float4 per node (full width)
#define V4H  (NB*DOUT/4)      // 512 float4 per node (half width)
#define XPS  ((size_t)MM*FF)   // X plane elems per stage
#define HPS  ((size_t)MM*DOUT) // H plane elems per stage

typedef unsigned long long u64;
typedef unsigned int u32;

// ---------------- scratch (device globals; allocation-free) ----------------
__device__ __align__(16) float g_X[2][XPS];    // X0, X1 fp32 (conv operands)
__device__ __align__(16) float g_H[2][HPS];    // RH, D1 fp32 (conv operands)
__device__ __align__(16) float g_Z[HPS];       // update gate z
// bf16 hi/lo planes (GEMM A/B operands, pre-split by producers)
__device__ __align__(16) __nv_bfloat16 g_Xp[2][3][XPS];   // [hi/lo][s]
__device__ __align__(16) __nv_bfloat16 g_Hp[2][3][HPS];
__device__ __align__(16) __nv_bfloat16 g_Wgp[2][128*384];
__device__ __align__(16) __nv_bfloat16 g_Wcp[2][64*384];
__device__ int    g_cnt[NN];
__device__ int    g_rs [NN+1];
__device__ int    g_cur[NN];
__device__ __align__(8) float2 g_epack[NE];   // {col as int bits, weight}

// ---------------- bf16 hi/lo split helpers ----------------
__device__ __forceinline__ unsigned packhi2(float a, float b, float& ra, float& rb) {
    __nv_bfloat16 ha = __float2bfloat16(a), hb = __float2bfloat16(b);
    ra = a - __bfloat162float(ha);
    rb = b - __bfloat162float(hb);
    __nv_bfloat162 t = __halves2bfloat162(ha, hb);
    return *reinterpret_cast<unsigned*>(&t);
}
__device__ __forceinline__ unsigned packlo2(float a, float b) {
    __nv_bfloat162 t = __floats2bfloat162_rn(a, b);
    return *reinterpret_cast<unsigned*>(&t);
}
// emit float4 -> hi/lo planes at element offset po (multiple of 4)
__device__ __forceinline__ void emit_planes(float4 v, __nv_bfloat16* hp,
                                            __nv_bfloat16* lp, size_t po) {
    float r0, r1, r2, r3;
    unsigned h0 = packhi2(v.x, v.y, r0, r1);
    unsigned h1 = packhi2(v.z, v.w, r2, r3);
    *(uint2*)&hp[po] = make_uint2(h0, h1);
    *(uint2*)&lp[po] = make_uint2(packlo2(r0, r1), packlo2(r2, r3));
}

__device__ __forceinline__ u32 smem_u32(const void* p) {
    u32 a;
    asm("{ .reg .u64 t; cvta.to.shared.u64 t, %1; cvt.u32.u64 %0, t; }"
        : "=r"(a) : "l"(p));
    return a;
}
__device__ __forceinline__ void cpa16(u32 dst, const void* src) {
    asm volatile("cp.async.ca.shared.global [%0], [%1], 16;"
                 :: "r"(dst), "l"(src) : "memory");
}
#define CP_WAIT() do { \
    asm volatile("cp.async.commit_group;" ::: "memory"); \
    asm volatile("cp.async.wait_group 0;"  ::: "memory"); \
} while (0)

// mma.sync m16n8k16 row.col f32.bf16.bf16.f32 (family PTX, sm_80+)
__device__ __forceinline__ void mma_bf16(float* c,
        u32 a0, u32 a1, u32 a2, u32 a3, u32 b0, u32 b1) {
    asm volatile("mma.sync.aligned.m16n8k16.row.col.f32.bf16.bf16.f32 "
        "{%0,%1,%2,%3}, {%4,%5,%6,%7}, {%8,%9}, {%0,%1,%2,%3};"
        : "+f"(c[0]), "+f"(c[1]), "+f"(c[2]), "+f"(c[3])
        : "r"(a0), "r"(a1), "r"(a2), "r"(a3), "r"(b0), "r"(b1));
}

// ---------------- fast activations ----------------
__device__ __forceinline__ float fast_sigmoid(float g) {
    return __fdividef(1.f, 1.f + __expf(-g));
}
__device__ __forceinline__ float fast_tanh(float x) {
    float t = __expf(-2.f * fabsf(x));
    float r = __fdividef(1.f - t, 1.f + t);
    return copysignf(r, x);
}

// ---------------- kernel 1: histogram (+dtype detect) / build X0 + planes ------
#define HIST_BLKS (NE/256)     // 625
__global__ void k_histbuild(const long long* __restrict__ ei64,
                            const float* __restrict__ in,
                            const float* __restrict__ hx) {
    if (blockIdx.x < HIST_BLKS) {
        __shared__ int bad;
        if (threadIdx.x == 0) bad = 0;
        __syncthreads();
        long long v = ei64[threadIdx.x];
        if (v < 0 || v >= NN) atomicOr(&bad, 1);
        __syncthreads();
        int e = blockIdx.x*256 + threadIdx.x;
        int r;
        if (bad) r = ((const int*)ei64)[e];
        else     r = (int)ei64[e];
        atomicAdd(&g_cnt[r], 1);
    } else {
        int n = blockIdx.x - HIST_BLKS;
        const float4* in4 = (const float4*)in;
        const float4* hx4 = (const float4*)hx;
        for (int i = threadIdx.x; i < 512; i += 256) {
            int b = i >> 4, f4 = i & 15;
            size_t m = (size_t)n*32 + b;
            size_t po = m*FF + f4*4;
            float4 v = __ldg(&in4[((size_t)b*NN + n)*16 + f4]);
            *(float4*)&g_X[0][po] = v;
            emit_planes(v, g_Xp[0][0], g_Xp[1][0], po);
            float4 w = __ldg(&hx4[((size_t)b*NN + n)*16 + f4]);
            *(float4*)&g_X[0][po + 64] = w;
            emit_planes(w, g_Xp[0][0], g_Xp[1][0], po + 64);
        }
    }
}

// ---------------- kernel 2: scan + CSR fill + weight planes + re-zero cnt ------
__global__ void k_scanfill(const long long* __restrict__ ei64,
                           const float* __restrict__ ew,
                           const float* __restrict__ Wg,
                           const float* __restrict__ Wc) {
    __shared__ int sums[1024];
    __shared__ int bad;
    int t = threadIdx.x;
    if (t == 0) bad = 0;
    __syncthreads();
    if (t < 256) {
        long long v = ei64[t];
        if (v < 0 || v >= NN) atomicOr(&bad, 1);
    }
    const int CH = 10;
    int base = t*CH;
    int loc[CH];
    int s = 0;
    #pragma unroll
    for (int i = 0; i < CH; i++) {
        int idx = base + i;
        int v = (idx < NN) ? g_cnt[idx] : 0;
        loc[i] = s; s += v;
    }
    sums[t] = s;
    __syncthreads();
    for (int off = 1; off < 1024; off <<= 1) {
        int v = (t >= off) ? sums[t-off] : 0;
        __syncthreads();
        sums[t] += v;
        __syncthreads();
    }
    int prev = (t > 0) ? sums[t-1] : 0;
    #pragma unroll
    for (int i = 0; i < CH; i++) {
        int idx = base + i;
        if (idx < NN) {
            int v = prev + loc[i];
            g_rs[idx] = v;
            g_cur[idx] = v;
        }
    }
    if (t == 1023) g_rs[NN] = sums[1023];
    __syncthreads();
    for (int i = t; i < NN; i += 1024) g_cnt[i] = 0;   // for next replay
    // weight planes
    for (int e = t; e < 128*384; e += 1024) {
        float v = Wg[e];
        __nv_bfloat16 h = __float2bfloat16(v);
        g_Wgp[0][e] = h;
        g_Wgp[1][e] = __float2bfloat16(v - __bfloat162float(h));
    }
    for (int e = t; e < 64*384; e += 1024) {
        float v = Wc[e];
        __nv_bfloat16 h = __float2bfloat16(v);
        g_Wcp[0][e] = h;
        g_Wcp[1][e] = __float2bfloat16(v - __bfloat162float(h));
    }
    int is64 = !bad;
    for (int e = t; e < NE; e += 1024) {
        int r, c;
        if (is64) {
            r = (int)ei64[e];
            c = (int)ei64[NE + e];
        } else {
            r = ((const int*)ei64)[e];
            c = ((const int*)ei64)[NE + e];
        }
        int pos = atomicAdd(&g_cur[r], 1);
        g_epack[pos] = make_float2(__int_as_float(c), ew[e]);
    }
}

// ---------------- graph conv (CSR gather-reduce, feature-sliced, 2-edge) -------
// fp32 out optional; always emits bf16 hi/lo planes
#define CONV_FMA(acc, p, v) \
    acc.x = fmaf(p.y, v.x, acc.x); acc.y = fmaf(p.y, v.y, acc.y); \
    acc.z = fmaf(p.y, v.z, acc.z); acc.w = fmaf(p.y, v.w, acc.w);

template<int NV4>
__global__ __launch_bounds__(256) void k_conv(const float4* __restrict__ x,
                       const float4* __restrict__ base,
                       float4* __restrict__ out,
                       __nv_bfloat16* __restrict__ php,
                       __nv_bfloat16* __restrict__ plp,
                       float scale, int sub) {
    int n   = blockIdx.x;
    int idx = blockIdx.y*256 + threadIdx.x;
    const float4* xb = x + idx;
    float4 acc = make_float4(0.f, 0.f, 0.f, 0.f);
    int e0 = __ldg(&g_rs[n]);
    int e1 = __ldg(&g_rs[n+1]);
    int e = e0;
    for (; e + 2 <= e1; e += 2) {
        float2 p0 = __ldg(&g_epack[e]);
        float2 p1 = __ldg(&g_epack[e+1]);
        float4 v0 = __ldg(xb + __float_as_int(p0.x)*NV4);
        float4 v1 = __ldg(xb + __float_as_int(p1.x)*NV4);
        CONV_FMA(acc, p0, v0)
        CONV_FMA(acc, p1, v1)
    }
    if (e < e1) {
        float2 p0 = __ldg(&g_epack[e]);
        float4 v0 = __ldg(xb + __float_as_int(p0.x)*NV4);
        CONV_FMA(acc, p0, v0)
    }
    float4 r;
    if (sub) {
        float4 b = __ldg(&base[n*NV4 + idx]);
        r = make_float4(fmaf(scale, acc.x, -b.x), fmaf(scale, acc.y, -b.y),
                        fmaf(scale, acc.z, -b.z), fmaf(scale, acc.w, -b.w));
    } else {
        r = make_float4(scale*acc.x, scale*acc.y, scale*acc.z, scale*acc.w);
    }
    if (out) __stcs(&out[n*NV4 + idx], r);
    // plane emission: node-row layout [m][k], k-width = NV4/8
    const int KW  = NV4/8;         // 128 or 64
    const int KW4 = KW/4;          // float4 per (m) row
    int b  = idx / KW4;
    int f4 = idx % KW4;
    size_t po = ((size_t)n*32 + b)*KW + f4*4;
    emit_planes(r, php, plp, po);
}

// ================= GEMM 1: gates via mma.sync bf16-split (plane staging) ======
// smem planes: 128 rows x 144 B pitch
//   AHI 0, ALO 18432, BHI 36864, BLO 55296 ; total 73728
extern __shared__ char dynsm[];

__global__ __launch_bounds__(256, 2)
void k_gates_mma(const float* __restrict__ bg) {
    char* AHI = dynsm;
    char* ALO = dynsm + 18432;
    char* BHI = dynsm + 36864;
    char* BLO = dynsm + 55296;
    u32 sb = smem_u32(dynsm);
    u32 sAHI = sb, sALO = sb + 18432, sBHI = sb + 36864, sBLO = sb + 55296;
    int tid = threadIdx.x, wid = tid >> 5, lid = tid & 31;
    int g = lid >> 2, t = lid & 3;
    int m0 = blockIdx.x * 128;
    int rb = wid & 3, cb = wid >> 2;

    float acc[2][8][4];
    #pragma unroll
    for (int i = 0; i < 2; i++)
        #pragma unroll
        for (int j = 0; j < 8; j++)
            #pragma unroll
            for (int k = 0; k < 4; k++) acc[i][j][k] = 0.f;

    #pragma unroll 1
    for (int c = 0; c < 6; c++) {
        const __nv_bfloat16* Ah = &g_Xp[0][c >> 1][(c & 1)*64];
        const __nv_bfloat16* Al = &g_Xp[1][c >> 1][(c & 1)*64];
        #pragma unroll
        for (int i = 0; i < 4; i++) {
            int f = tid + 256*i;
            int r = f >> 3, c8 = f & 7;
            u32 d = r*144 + c8*16;
            size_t so = (size_t)(m0 + r)*FF + c8*8;
            int wo = r*384 + c*64 + c8*8;
            cpa16(sAHI + d, Ah + so);
            cpa16(sALO + d, Al + so);
            cpa16(sBHI + d, &g_Wgp[0][wo]);
            cpa16(sBLO + d, &g_Wgp[1][wo]);
        }
        CP_WAIT();
        __syncthreads();
        #pragma unroll
        for (int ks = 0; ks < 4; ks++) {
            int abase = (rb*32 + g)*144 + (ks*8 + t)*4;
            u32 ah[8], al[8];
            #pragma unroll
            for (int ma = 0; ma < 2; ma++) {
                int ro = abase + ma*2304;
                ah[ma*4+0] = *(const u32*)(AHI + ro);
                ah[ma*4+1] = *(const u32*)(AHI + ro + 1152);
                ah[ma*4+2] = *(const u32*)(AHI + ro + 16);
                ah[ma*4+3] = *(const u32*)(AHI + ro + 1152 + 16);
                al[ma*4+0] = *(const u32*)(ALO + ro);
                al[ma*4+1] = *(const u32*)(ALO + ro + 1152);
                al[ma*4+2] = *(const u32*)(ALO + ro + 16);
                al[ma*4+3] = *(const u32*)(ALO + ro + 1152 + 16);
            }
            #pragma unroll
            for (int na = 0; na < 8; na++) {
                int bbase = (cb*64 + na*8 + g)*144 + (ks*8 + t)*4;
                u32 bh0 = *(const u32*)(BHI + bbase);
                u32 bh1 = *(const u32*)(BHI + bbase + 16);
                u32 bl0 = *(const u32*)(BLO + bbase);
                u32 bl1 = *(const u32*)(BLO + bbase + 16);
                mma_bf16(acc[0][na], ah[0], ah[1], ah[2], ah[3], bh0, bh1);
                mma_bf16(acc[1][na], ah[4], ah[5], ah[6], ah[7], bh0, bh1);
                mma_bf16(acc[0][na], ah[0], ah[1], ah[2], ah[3], bl0, bl1);
                mma_bf16(acc[1][na], ah[4], ah[5], ah[6], ah[7], bl0, bl1);
                mma_bf16(acc[0][na], al[0], al[1], al[2], al[3], bh0, bh1);
                mma_bf16(acc[1][na], al[4], al[5], al[6], al[7], bh0, bh1);
            }
        }
        __syncthreads();
    }

    // epilogue: sigmoid; cb==0 -> z ; cb==1 -> RH = r*hx (fp32 + planes)
    #pragma unroll
    for (int ma = 0; ma < 2; ma++) {
        #pragma unroll
        for (int gg = 0; gg < 2; gg++) {
            size_t m = (size_t)(m0 + rb*32 + ma*16 + g + gg*8);
            #pragma unroll
            for (int na = 0; na < 8; na++) {
                int col = cb*64 + na*8 + 2*t;
                float s0 = fast_sigmoid(acc[ma][na][2*gg+0] + __ldg(&bg[col]));
                float s1 = fast_sigmoid(acc[ma][na][2*gg+1] + __ldg(&bg[col+1]));
                if (cb == 0) {
                    *(float2*)&g_Z[m*DOUT + col] = make_float2(s0, s1);
                } else {
                    int cc = col - 64;
                    float2 hv = *(const float2*)&g_X[0][m*FF + 64 + cc];
                    float rh0 = s0*hv.x, rh1 = s1*hv.y;
                    *(float2*)&g_H[0][m*DOUT + cc] = make_float2(rh0, rh1);
                    float q0, q1;
                    unsigned hh = packhi2(rh0, rh1, q0, q1);
                    *(unsigned*)&g_Hp[0][0][m*DOUT + cc] = hh;
                    *(unsigned*)&g_Hp[1][0][m*DOUT + cc] = packlo2(q0, q1);
                }
            }
        }
    }
}

// ================= GEMM 2: candidate via mma.sync bf16-split + combine ========
// smem: AHI 0, ALO 18432, BHI 36864 (64x144), BLO 46080 ; total 55296
__global__ __launch_bounds__(256, 2)
void k_cand_mma(const float* __restrict__ bc, float* __restrict__ out) {
    char* AHI = dynsm;
    char* ALO = dynsm + 18432;
    char* BHI = dynsm + 36864;
    char* BLO = dynsm + 46080;
    u32 sb = smem_u32(dynsm);
    u32 sAHI = sb, sALO = sb + 18432, sBHI = sb + 36864, sBLO = sb + 46080;
    int tid = threadIdx.x, wid = tid >> 5, lid = tid & 31;
    int g = lid >> 2, t = lid & 3;
    int m0 = blockIdx.x * 128;
    int rb = wid & 3, cb = wid >> 2;

    float acc[2][4][4];
    #pragma unroll
    for (int i = 0; i < 2; i++)
        #pragma unroll
        for (int j = 0; j < 4; j++)
            #pragma unroll
            for (int k = 0; k < 4; k++) acc[i][j][k] = 0.f;

    #pragma unroll 1
    for (int c = 0; c < 6; c++) {
        const __nv_bfloat16 *Ah, *Al;
        int rs;
        if ((c & 1) == 0) { Ah = g_Xp[0][c >> 1]; Al = g_Xp[1][c >> 1]; rs = FF; }
        else              { Ah = g_Hp[0][c >> 1]; Al = g_Hp[1][c >> 1]; rs = DOUT; }
        #pragma unroll
        for (int i = 0; i < 4; i++) {
            int f = tid + 256*i;
            int r = f >> 3, c8 = f & 7;
            u32 d = r*144 + c8*16;
            size_t so = (size_t)(m0 + r)*rs + c8*8;
            cpa16(sAHI + d, Ah + so);
            cpa16(sALO + d, Al + so);
        }
        #pragma unroll
        for (int i = 0; i < 2; i++) {
            int f = tid + 256*i;
            int r = f >> 3, c8 = f & 7;
            u32 d = r*144 + c8*16;
            int wo = r*384 + c*64 + c8*8;
            cpa16(sBHI + d, &g_Wcp[0][wo]);
            cpa16(sBLO + d, &g_Wcp[1][wo]);
        }
        CP_WAIT();
        __syncthreads();
        #pragma unroll
        for (int ks = 0; ks < 4; ks++) {
            int abase = (rb*32 + g)*144 + (ks*8 + t)*4;
            u32 ah[8], al[8];
            #pragma unroll
            for (int ma = 0; ma < 2; ma++) {
                int ro = abase + ma*2304;
                ah[ma*4+0] = *(const u32*)(AHI + ro);
                ah[ma*4+1] = *(const u32*)(AHI + ro + 1152);
                ah[ma*4+2] = *(const u32*)(AHI + ro + 16);
                ah[ma*4+3] = *(const u32*)(AHI + ro + 1152 + 16);
                al[ma*4+0] = *(const u32*)(ALO + ro);
                al[ma*4+1] = *(const u32*)(ALO + ro + 1152);
                al[ma*4+2] = *(const u32*)(ALO + ro + 16);
                al[ma*4+3] = *(const u32*)(ALO + ro + 1152 + 16);
            }
            #pragma unroll
            for (int na = 0; na < 4; na++) {
                int bbase = (cb*32 + na*8 + g)*144 + (ks*8 + t)*4;
                u32 bh0 = *(const u32*)(BHI + bbase);
                u32 bh1 = *(const u32*)(BHI + bbase + 16);
                u32 bl0 = *(const u32*)(BLO + bbase);
                u32 bl1 = *(const u32*)(BLO + bbase + 16);
                mma_bf16(acc[0][na], ah[0], ah[1], ah[2], ah[3], bh0, bh1);
                mma_bf16(acc[1][na], ah[4], ah[5], ah[6], ah[7], bh0, bh1);
                mma_bf16(acc[0][na], ah[0], ah[1], ah[2], ah[3], bl0, bl1);
                mma_bf16(acc[1][na], ah[4], ah[5], ah[6], ah[7], bl0, bl1);
                mma_bf16(acc[0][na], al[0], al[1], al[2], al[3], bh0, bh1);
                mma_bf16(acc[1][na], al[4], al[5], al[6], al[7], bh0, bh1);
            }
        }
        __syncthreads();
    }

    // epilogue: tanh, gate combine, write (B, N, 64) layout
    #pragma unroll
    for (int ma = 0; ma < 2; ma++) {
        #pragma unroll
        for (int gg = 0; gg < 2; gg++) {
            size_t m = (size_t)(m0 + rb*32 + ma*16 + g + gg*8);
            int n = (int)(m >> 5);
            int b = (int)(m & 31);
            #pragma unroll
            for (int na = 0; na < 4; na++) {
                int col = cb*32 + na*8 + 2*t;
                float cd0 = fast_tanh(acc[ma][na][2*gg+0] + __ldg(&bc[col]));
                float cd1 = fast_tanh(acc[ma][na][2*gg+1] + __ldg(&bc[col+1]));
                float2 z2 = *(const float2*)&g_Z[m*DOUT + col];
                float2 h2 = *(const float2*)&g_X[0][m*FF + 64 + col];
                float2 r2 = make_float2((1.f - z2.x)*h2.x + z2.x*cd0,
                                        (1.f - z2.y)*h2.y + z2.y*cd1);
                *(float2*)&out[(size_t)b*(NN*DOUT) + (size_t)n*DOUT + col] = r2;
            }
        }
    }
}

// ---------------- launch ----------------
extern "C" void kernel_launch(void* const* d_in, const int* in_sizes, int n_in,
                              void* d_out, int out_size) {
    const float* inp = nullptr;
    const float* hx  = nullptr;
    const void*  ei  = nullptr;
    const float* ew  = nullptr;
    const float* Wg  = nullptr;
    const float* Wc  = nullptr;
    const float* bg  = nullptr;
    const float* bc  = nullptr;
    for (int i = 0; i < n_in; i++) {
        switch (in_sizes[i]) {
            case 20480000: if (!inp) inp = (const float*)d_in[i];
                           else      hx  = (const float*)d_in[i]; break;
            case 320000:   ei = d_in[i];                 break;
            case 160000:   ew = (const float*)d_in[i];   break;
            case 49152:    Wg = (const float*)d_in[i];   break;
            case 24576:    Wc = (const float*)d_in[i];   break;
            case 128:      bg = (const float*)d_in[i];   break;
            case 64:       bc = (const float*)d_in[i];   break;
            default: break;
        }
    }
    float* out = (float*)d_out;

    void *pX, *pH, *pXp, *pHp;
    cudaGetSymbolAddress(&pX, g_X);
    cudaGetSymbolAddress(&pH, g_H);
    cudaGetSymbolAddress(&pXp, g_Xp);
    cudaGetSymbolAddress(&pHp, g_Hp);
    float* X = (float*)pX;
    float* H = (float*)pH;
    __nv_bfloat16* Xp = (__nv_bfloat16*)pXp;   // [hi/lo][s][XPS]
    __nv_bfloat16* Hp = (__nv_bfloat16*)pHp;

    cudaFuncSetAttribute(k_gates_mma, cudaFuncAttributeMaxDynamicSharedMemorySize, 73728);
    cudaFuncSetAttribute(k_cand_mma,  cudaFuncAttributeMaxDynamicSharedMemorySize, 55296);

    // 1-2: CSR + X0 (+ planes) + weight planes
    k_histbuild<<<HIST_BLKS + NN, 256>>>((const long long*)ei, inp, hx);
    k_scanfill<<<1, 1024>>>((const long long*)ei, ew, Wg, Wc);

    // 3-4: first diffusion (X1 fp32+planes; X2 planes only)
    dim3 gf(NN, 4);
    k_conv<V4F><<<gf, 256>>>((const float4*)X,          nullptr,
                             (float4*)(X + XPS),
                             Xp + 1*XPS, Xp + (3+1)*XPS, 1.f, 0);
    k_conv<V4F><<<gf, 256>>>((const float4*)(X + XPS),  (const float4*)X,
                             nullptr,
                             Xp + 2*XPS, Xp + (3+2)*XPS, 2.f, 1);

    // 5: gates GEMM (tensor cores) -> z, RH (fp32 + planes)
    k_gates_mma<<<MM/128, 256, 73728>>>(bg);

    // 6-7: second diffusion on RH (D1 fp32+planes; D2 planes only)
    dim3 gh(NN, 2);
    k_conv<V4H><<<gh, 256>>>((const float4*)H,          nullptr,
                             (float4*)(H + HPS),
                             Hp + 1*HPS, Hp + (3+1)*HPS, 1.f, 0);
    k_conv<V4H><<<gh, 256>>>((const float4*)(H + HPS),  (const float4*)H,
                             nullptr,
                             Hp + 2*HPS, Hp + (3+2)*HPS, 2.f, 1);

    // 8: candidate GEMM + combine + transpose
    k_cand_mma<<<MM/128, 256, 55296>>>(bc, out);
}